// round 12
// baseline (speedup 1.0000x reference)
#include <cuda_runtime.h>
#include <cuda_fp16.h>
#include <cstdint>

#define GS     256
#define NCLS   10
#define NPTS   262144            // 2^18
#define BATCH  16
#define CELLS  (GS * GS)         // 65536
#define TCELLS (BATCH * CELLS)   // 1,048,576
#define PTOT   (BATCH * NPTS)    // 4,194,304
#define CAP    16                // Poisson(4): P(>16) ~ 1e-6
#define IMGS   (BATCH * NCLS)    // 160
#define OUTN   (IMGS * CELLS)    // 10,485,760 floats

// ---------------------------------------------------------------------------
// Scratch — SLOT-MAJOR 32B records (one sector each):
//   uint4 #0 : v0v1, v2v3, v4v5, v6v7   (half2 bit patterns)
//   uint4 #1 : v8v9 (half2), rx (f32 bits), ry (f32 bits), pad
// ---------------------------------------------------------------------------
__device__ uint32_t g_cursor[TCELLS];
__device__ __align__(128) uint4 g_pay[(size_t)CAP * TCELLS * 2];   // 512 MB

#define OUT4  (OUTN / 4)
#define CUR4  (TCELLS / 4)
__global__ __launch_bounds__(256)
void zero_out_kernel(float4* __restrict__ p, int n4) {
    const int i = blockIdx.x * blockDim.x + threadIdx.x;
    if (i < n4) p[i] = make_float4(0.f, 0.f, 0.f, 0.f);
}
__global__ __launch_bounds__(256)
void zero_cursor_kernel() {
    const int i = blockIdx.x * blockDim.x + threadIdx.x;
    if (i < CUR4) ((uint4*)g_cursor)[i] = make_uint4(0u, 0u, 0u, 0u);
}

__device__ __forceinline__ uint32_t h2bits(float a, float b) {
    __half2 h = __floats2half2_rn(a, b);
    return *reinterpret_cast<uint32_t*>(&h);
}
__device__ __forceinline__ float2 bits2f2(uint32_t u) {
    __half2 h = *reinterpret_cast<__half2*>(&u);
    return __half22float2(h);
}

// ---------------------------------------------------------------------------
// Pass A: scatter into fixed-capacity slot-major buckets; overflow -> atomics
// (identical to the 242.4us R10 version)
// ---------------------------------------------------------------------------
__global__ __launch_bounds__(256)
void scatter_kernel(const float* __restrict__ points,
                    const float* __restrict__ values,
                    float* __restrict__ out) {
    const int gid = blockIdx.x * blockDim.x + threadIdx.x;
    const int b = gid >> 18;
    const int n = gid & (NPTS - 1);

    const float* pb = points + (size_t)b * 2 * NPTS;
    const float fx = (pb[n] + 0.5f) * (float)GS;
    const float fy = (pb[NPTS + n] + 0.5f) * (float)GS;
    const float xf = floorf(fx);
    const float yf = floorf(fy);
    const int x = (int)xf;
    const int y = (int)yf;
    const float rx = fx - xf;
    const float ry = fy - yf;
    if (((unsigned)x >= GS) || ((unsigned)y >= GS)) return;

    const float* vb = values + (size_t)b * NCLS * NPTS + n;
    float v[10];
#pragma unroll
    for (int c = 0; c < NCLS; c++) v[c] = vb[(size_t)c * NPTS];

    const int cellg = (b << 16) + (y << 8) + x;
    const uint32_t slot = atomicAdd(&g_cursor[cellg], 1u);

    if (slot < CAP) {
        uint4* dst = &g_pay[((size_t)slot * TCELLS + cellg) * 2];
        const uint4 q0 = make_uint4(h2bits(v[0], v[1]), h2bits(v[2], v[3]),
                                    h2bits(v[4], v[5]), h2bits(v[6], v[7]));
        const uint4 q1 = make_uint4(h2bits(v[8], v[9]),
                                    __float_as_uint(rx), __float_as_uint(ry), 0u);
        __stcs(dst + 0, q0);
        __stcs(dst + 1, q1);
    } else {
        const bool vx1 = (x + 1) < GS;
        const bool vy1 = (y + 1) < GS;
        const float wx0 = 1.f - rx, wy0 = 1.f - ry;
        const float w00 = wx0 * wy0, w10 = rx * wy0, w01 = wx0 * ry, w11 = rx * ry;
        const int i00 = (y << 8) + x;
        float* ob = out + (size_t)b * NCLS * CELLS;
#pragma unroll
        for (int c = 0; c < NCLS; c++) {
            float* o = ob + ((size_t)c << 16);
            atomicAdd(o + i00, w00 * v[c]);
            if (vx1)        atomicAdd(o + i00 + 1,      w10 * v[c]);
            if (vy1)        atomicAdd(o + i00 + GS,     w01 * v[c]);
            if (vx1 && vy1) atomicAdd(o + i00 + GS + 1, w11 * v[c]);
        }
    }
}

// ---------------------------------------------------------------------------
// Pass B: fused reduce + corner-combine, TWO THREADS per cell (even/odd slots).
// Block = 512 threads = 2 halves x 256 cells (16x16 tile).
// Per-thread trips <= 8 (warp-max ~5 vs ~10 single-threaded) and 2 blocks/SM.
// Partials merged in the smem patch assembly (st[..][cell] + st[..][cell+256]).
// ---------------------------------------------------------------------------
__global__ __launch_bounds__(512, 2)
void reduce_kernel(float* __restrict__ out) {
    const int t = threadIdx.x;         // 0..511
    const int half = t >> 8;           // 0: even slots, 1: odd slots
    const int cell = t & 255;
    const int ly = cell >> 4;
    const int lx = cell & 15;

    const int blk = blockIdx.x;        // 0..4095
    const int b  = blk >> 8;
    const int tt = blk & 255;
    const int ty = tt >> 4;
    const int tx = tt & 15;

    const int cellg = (b << 16) + ((ty * 16 + ly) << 8) + (tx * 16 + lx);
    const uint32_t raw = g_cursor[cellg];
    const uint32_t cnt = raw < CAP ? raw : CAP;
    // this thread handles slots {2i + half}: even gets ceil(cnt/2), odd floor
    const uint32_t mycnt = half ? (cnt >> 1) : ((cnt + 1) >> 1);
    const uint32_t wmax = __reduce_max_sync(0xFFFFFFFFu, mycnt);

    float acc[4][NCLS];
#pragma unroll
    for (int k = 0; k < 4; k++)
#pragma unroll
        for (int c = 0; c < NCLS; c++) acc[k][c] = 0.f;

    for (uint32_t i = 0; i < wmax; i++) {
        if (i < mycnt) {
            const uint32_t slot = 2 * i + half;
            const uint4* rec = &g_pay[((size_t)slot * TCELLS + cellg) * 2];
            const uint4 q0 = __ldcs(rec + 0);
            const uint4 q1 = __ldcs(rec + 1);
            const float2 f01 = bits2f2(q0.x);
            const float2 f23 = bits2f2(q0.y);
            const float2 f45 = bits2f2(q0.z);
            const float2 f67 = bits2f2(q0.w);
            const float2 f89 = bits2f2(q1.x);
            const float rx = __uint_as_float(q1.y);
            const float ry = __uint_as_float(q1.z);
            const float wx0 = 1.f - rx, wy0 = 1.f - ry;
            const float w00 = wx0 * wy0, w10 = rx * wy0, w01 = wx0 * ry, w11 = rx * ry;
            const float v[10] = {f01.x, f01.y, f23.x, f23.y, f45.x,
                                 f45.y, f67.x, f67.y, f89.x, f89.y};
#pragma unroll
            for (int c = 0; c < NCLS; c++) {
                acc[0][c] += w00 * v[c];
                acc[1][c] += w10 * v[c];
                acc[2][c] += w01 * v[c];
                acc[3][c] += w11 * v[c];
            }
        }
    }

    // Two 5-class waves; st[k][cl][t] with t covering both halves (merge at read)
    __shared__ float st[4][5][512];    // 40 KB
#pragma unroll
    for (int wave = 0; wave < 2; wave++) {
#pragma unroll
        for (int k = 0; k < 4; k++)
#pragma unroll
            for (int cl = 0; cl < 5; cl++)
                st[k][cl][t] = acc[k][wave * 5 + cl];
        __syncthreads();

        // assemble 17x17 patch for 5 classes: 1445 outputs over 512 threads
        for (int w = t; w < 17 * 17 * 5; w += 512) {
            const int cl = w / 289;
            const int r  = w - 289 * cl;
            const int oy = r / 17;
            const int ox = r - 17 * oy;

            float v = 0.f;
            if (oy < 16 && ox < 16) {
                const int i0 = oy * 16 + ox;
                v += st[0][cl][i0] + st[0][cl][i0 + 256];
            }
            if (oy < 16 && ox >= 1) {
                const int i1 = oy * 16 + ox - 1;
                v += st[1][cl][i1] + st[1][cl][i1 + 256];
            }
            if (oy >= 1 && ox < 16) {
                const int i2 = (oy - 1) * 16 + ox;
                v += st[2][cl][i2] + st[2][cl][i2 + 256];
            }
            if (oy >= 1 && ox >= 1) {
                const int i3 = (oy - 1) * 16 + ox - 1;
                v += st[3][cl][i3] + st[3][cl][i3 + 256];
            }

            const int Y = ty * 16 + oy;
            const int X = tx * 16 + ox;
            if (Y > 255 || X > 255) continue;

            const int c2 = wave * 5 + cl;
            float* dst = out + (((size_t)(b * NCLS + c2)) << 16) + (Y << 8) + X;
            const bool excl = (oy != 16) && (ox != 16) &&
                              (oy != 0 || ty == 0) && (ox != 0 || tx == 0);
            if (excl) *dst = v + *dst;
            else      atomicAdd(dst, v);
        }
        __syncthreads();   // protect st before next wave overwrites
    }
}

// ---------------------------------------------------------------------------
// Harness entry. Launch order puts reduce at idx 3 (ncu capture slot).
// ---------------------------------------------------------------------------
extern "C" void kernel_launch(void* const* d_in, const int* in_sizes, int n_in,
                              void* d_out, int out_size) {
    const float* points = (const float*)d_in[0];
    const float* values = (const float*)d_in[1];
    float* out = (float*)d_out;

    zero_out_kernel<<<(OUT4 + 255) / 256, 256>>>((float4*)out, OUT4);   // idx 0
    zero_cursor_kernel<<<(CUR4 + 255) / 256, 256>>>();                  // idx 1
    scatter_kernel<<<PTOT / 256, 256>>>(points, values, out);           // idx 2
    reduce_kernel<<<TCELLS / 256, 512>>>(out);                          // idx 3 (profiled)
}

// round 13
// speedup vs baseline: 1.3542x; 1.3542x over previous
#include <cuda_runtime.h>
#include <cuda_fp16.h>
#include <cstdint>

#define GS     256
#define NCLS   10
#define NPTS   262144            // 2^18
#define BATCH  16
#define CELLS  (GS * GS)         // 65536
#define TCELLS (BATCH * CELLS)   // 1,048,576
#define PTOT   (BATCH * NPTS)    // 4,194,304
#define CAP    16                // Poisson(4): P(>16) ~ 1e-6
#define IMGS   (BATCH * NCLS)    // 160
#define OUTN   (IMGS * CELLS)    // 10,485,760 floats
#define OVFMAX 8192

// ---------------------------------------------------------------------------
// Scratch — SLOT-MAJOR 32B records (one sector each):
//   uint4 #0 : v0v1, v2v3, v4v5, v6v7   (half2 bit patterns)
//   uint4 #1 : v8v9 (half2), rx (f32 bits), ry (f32 bits), pad
// ---------------------------------------------------------------------------
__device__ uint32_t g_cursor[TCELLS];
__device__ __align__(128) uint4 g_pay[(size_t)CAP * TCELLS * 2];   // 512 MB
__device__ uint32_t g_ovf_cnt;
__device__ float g_ovf[OVFMAX][16];   // cellg(bits), rx, ry, v0..v9

#define CUR4  (TCELLS / 4)
__global__ __launch_bounds__(256)
void zero_cursor_kernel() {
    const int i = blockIdx.x * blockDim.x + threadIdx.x;
    if (i < CUR4) ((uint4*)g_cursor)[i] = make_uint4(0u, 0u, 0u, 0u);
    if (i == 0) g_ovf_cnt = 0u;
}

// Zero only the tile frame: pixels with X%16==0 or Y%16==0 (atomic targets).
// Interior pixels are written with plain stores by the reduce.
__global__ __launch_bounds__(256)
void zero_frame_kernel(float* __restrict__ out) {
    const int o = blockIdx.x * blockDim.x + threadIdx.x;   // 0..OUTN-1
    if (o >= OUTN) return;
    const int idx = o & (CELLS - 1);
    const int X = idx & 255;
    const int Y = idx >> 8;
    if ((X & 15) == 0 || (Y & 15) == 0) out[o] = 0.f;
}

__device__ __forceinline__ uint32_t h2bits(float a, float b) {
    __half2 h = __floats2half2_rn(a, b);
    return *reinterpret_cast<uint32_t*>(&h);
}
__device__ __forceinline__ float2 bits2f2(uint32_t u) {
    __half2 h = *reinterpret_cast<__half2*>(&u);
    return __half22float2(h);
}

// ---------------------------------------------------------------------------
// Pass A: scatter into fixed-capacity slot-major buckets; overflow -> list
// ---------------------------------------------------------------------------
__global__ __launch_bounds__(256)
void scatter_kernel(const float* __restrict__ points,
                    const float* __restrict__ values) {
    const int gid = blockIdx.x * blockDim.x + threadIdx.x;
    const int b = gid >> 18;
    const int n = gid & (NPTS - 1);

    const float* pb = points + (size_t)b * 2 * NPTS;
    const float fx = (pb[n] + 0.5f) * (float)GS;
    const float fy = (pb[NPTS + n] + 0.5f) * (float)GS;
    const float xf = floorf(fx);
    const float yf = floorf(fy);
    const int x = (int)xf;
    const int y = (int)yf;
    const float rx = fx - xf;
    const float ry = fy - yf;
    if (((unsigned)x >= GS) || ((unsigned)y >= GS)) return;

    const float* vb = values + (size_t)b * NCLS * NPTS + n;
    float v[10];
#pragma unroll
    for (int c = 0; c < NCLS; c++) v[c] = vb[(size_t)c * NPTS];

    const int cellg = (b << 16) + (y << 8) + x;
    const uint32_t slot = atomicAdd(&g_cursor[cellg], 1u);

    if (slot < CAP) {
        uint4* dst = &g_pay[((size_t)slot * TCELLS + cellg) * 2];
        const uint4 q0 = make_uint4(h2bits(v[0], v[1]), h2bits(v[2], v[3]),
                                    h2bits(v[4], v[5]), h2bits(v[6], v[7]));
        const uint4 q1 = make_uint4(h2bits(v[8], v[9]),
                                    __float_as_uint(rx), __float_as_uint(ry), 0u);
        __stcs(dst + 0, q0);
        __stcs(dst + 1, q1);
    } else {
        // rare overflow (expect ~0-10 points): append full-precision record
        const uint32_t oi = atomicAdd(&g_ovf_cnt, 1u);
        if (oi < OVFMAX) {
            float* r = g_ovf[oi];
            r[0] = __uint_as_float((uint32_t)cellg);
            r[1] = rx;  r[2] = ry;
#pragma unroll
            for (int c = 0; c < NCLS; c++) r[3 + c] = v[c];
        }
    }
}

// ---------------------------------------------------------------------------
// Pass B: fused reduce + corner-combine, one THREAD per CELL (R10 structure)
// + unroll-2 batched loads for MLP. Interior = pure store; frame = atomicAdd.
// ---------------------------------------------------------------------------
__global__ __launch_bounds__(256)
void reduce_kernel(float* __restrict__ out) {
    const int t = threadIdx.x;
    const int ly = t >> 4;
    const int lx = t & 15;

    const int blk = blockIdx.x;        // 0..4095
    const int b  = blk >> 8;
    const int tt = blk & 255;
    const int ty = tt >> 4;
    const int tx = tt & 15;

    const int cellg = (b << 16) + ((ty * 16 + ly) << 8) + (tx * 16 + lx);
    const uint32_t raw = g_cursor[cellg];
    const uint32_t cnt = raw < CAP ? raw : CAP;
    const uint32_t wmax = __reduce_max_sync(0xFFFFFFFFu, cnt);

    float acc[4][NCLS];
#pragma unroll
    for (int k = 0; k < 4; k++)
#pragma unroll
        for (int c = 0; c < NCLS; c++) acc[k][c] = 0.f;

    for (uint32_t i = 0; i < wmax; i += 2) {
        uint4 q0a, q1a, q0b, q1b;
        const bool pa  = (i < cnt);
        const bool pb2 = (i + 1 < cnt);
        if (pa) {                       // batch both records' loads first (MLP)
            const uint4* ra = &g_pay[((size_t)i * TCELLS + cellg) * 2];
            q0a = __ldcs(ra + 0);
            q1a = __ldcs(ra + 1);
        }
        if (pb2) {
            const uint4* rb = &g_pay[((size_t)(i + 1) * TCELLS + cellg) * 2];
            q0b = __ldcs(rb + 0);
            q1b = __ldcs(rb + 1);
        }
        if (pa) {
            const float2 f01 = bits2f2(q0a.x), f23 = bits2f2(q0a.y);
            const float2 f45 = bits2f2(q0a.z), f67 = bits2f2(q0a.w);
            const float2 f89 = bits2f2(q1a.x);
            const float rx = __uint_as_float(q1a.y);
            const float ry = __uint_as_float(q1a.z);
            const float wx0 = 1.f - rx, wy0 = 1.f - ry;
            const float w00 = wx0 * wy0, w10 = rx * wy0, w01 = wx0 * ry, w11 = rx * ry;
            const float v[10] = {f01.x, f01.y, f23.x, f23.y, f45.x,
                                 f45.y, f67.x, f67.y, f89.x, f89.y};
#pragma unroll
            for (int c = 0; c < NCLS; c++) {
                acc[0][c] += w00 * v[c];
                acc[1][c] += w10 * v[c];
                acc[2][c] += w01 * v[c];
                acc[3][c] += w11 * v[c];
            }
        }
        if (pb2) {
            const float2 f01 = bits2f2(q0b.x), f23 = bits2f2(q0b.y);
            const float2 f45 = bits2f2(q0b.z), f67 = bits2f2(q0b.w);
            const float2 f89 = bits2f2(q1b.x);
            const float rx = __uint_as_float(q1b.y);
            const float ry = __uint_as_float(q1b.z);
            const float wx0 = 1.f - rx, wy0 = 1.f - ry;
            const float w00 = wx0 * wy0, w10 = rx * wy0, w01 = wx0 * ry, w11 = rx * ry;
            const float v[10] = {f01.x, f01.y, f23.x, f23.y, f45.x,
                                 f45.y, f67.x, f67.y, f89.x, f89.y};
#pragma unroll
            for (int c = 0; c < NCLS; c++) {
                acc[0][c] += w00 * v[c];
                acc[1][c] += w10 * v[c];
                acc[2][c] += w01 * v[c];
                acc[3][c] += w11 * v[c];
            }
        }
    }

    // stage: st[corner][class][cell] (stride-1 in cell -> conflict-free)
    __shared__ float st[4][NCLS][256];
#pragma unroll
    for (int k = 0; k < 4; k++)
#pragma unroll
        for (int c = 0; c < NCLS; c++) st[k][c][t] = acc[k][c];
    __syncthreads();

    // assemble 17x17 patch per class: 2890 outputs over 256 threads
    for (int w = t; w < 17 * 17 * NCLS; w += 256) {
        const int c2 = w / 289;
        const int r  = w - 289 * c2;
        const int oy = r / 17;
        const int ox = r - 17 * oy;

        float v = 0.f;
        if (oy < 16 && ox < 16)   v += st[0][c2][oy * 16 + ox];
        if (oy < 16 && ox >= 1)   v += st[1][c2][oy * 16 + ox - 1];
        if (oy >= 1 && ox < 16)   v += st[2][c2][(oy - 1) * 16 + ox];
        if (oy >= 1 && ox >= 1)   v += st[3][c2][(oy - 1) * 16 + ox - 1];

        const int Y = ty * 16 + oy;
        const int X = tx * 16 + ox;
        if (Y > 255 || X > 255) continue;

        float* dst = out + (((size_t)(b * NCLS + c2)) << 16) + (Y << 8) + X;
        const bool excl = (oy != 16) && (ox != 16) &&
                          (oy != 0 || ty == 0) && (ox != 0 || tx == 0);
        if (excl) *dst = v;             // pure store (frame pre-zeroed; no RMW)
        else      atomicAdd(dst, v);
    }
}

// ---------------------------------------------------------------------------
// Pass C: apply rare overflow records with direct atomics (after reduce)
// ---------------------------------------------------------------------------
__global__ __launch_bounds__(256)
void ovf_kernel(float* __restrict__ out) {
    const uint32_t cnt = g_ovf_cnt < OVFMAX ? g_ovf_cnt : OVFMAX;
    for (uint32_t i = threadIdx.x; i < cnt; i += 256) {
        const float* r = g_ovf[i];
        const uint32_t cellg = __float_as_uint(r[0]);
        const int b = cellg >> 16;
        const int y = (cellg >> 8) & 255;
        const int x = cellg & 255;
        const float rx = r[1], ry = r[2];
        const bool vx1 = (x + 1) < GS;
        const bool vy1 = (y + 1) < GS;
        const float wx0 = 1.f - rx, wy0 = 1.f - ry;
        const float w00 = wx0 * wy0, w10 = rx * wy0, w01 = wx0 * ry, w11 = rx * ry;
        const int i00 = (y << 8) + x;
        float* ob = out + (size_t)b * NCLS * CELLS;
#pragma unroll
        for (int c = 0; c < NCLS; c++) {
            const float v = r[3 + c];
            float* o = ob + ((size_t)c << 16);
            atomicAdd(o + i00, w00 * v);
            if (vx1)        atomicAdd(o + i00 + 1,      w10 * v);
            if (vy1)        atomicAdd(o + i00 + GS,     w01 * v);
            if (vx1 && vy1) atomicAdd(o + i00 + GS + 1, w11 * v);
        }
    }
}

// ---------------------------------------------------------------------------
// Harness entry. Launch order puts reduce at idx 3 (ncu capture slot).
// ---------------------------------------------------------------------------
extern "C" void kernel_launch(void* const* d_in, const int* in_sizes, int n_in,
                              void* d_out, int out_size) {
    const float* points = (const float*)d_in[0];
    const float* values = (const float*)d_in[1];
    float* out = (float*)d_out;

    zero_frame_kernel<<<(OUTN + 255) / 256, 256>>>(out);                 // idx 0
    zero_cursor_kernel<<<(CUR4 + 255) / 256, 256>>>();                   // idx 1
    scatter_kernel<<<PTOT / 256, 256>>>(points, values);                 // idx 2
    reduce_kernel<<<TCELLS / 256, 256>>>(out);                           // idx 3 (profiled)
    ovf_kernel<<<1, 256>>>(out);                                         // idx 4
}

// round 14
// speedup vs baseline: 1.5471x; 1.1424x over previous
#include <cuda_runtime.h>
#include <cuda_fp16.h>
#include <cstdint>

#define GS     256
#define NCLS   10
#define NPTS   262144            // 2^18
#define BATCH  16
#define CELLS  (GS * GS)         // 65536
#define TCELLS (BATCH * CELLS)   // 1,048,576
#define PTOT   (BATCH * NPTS)    // 4,194,304
#define CAP    16                // Poisson(4): P(>16) ~ 1e-6
#define IMGS   (BATCH * NCLS)    // 160
#define OUTN   (IMGS * CELLS)    // 10,485,760 floats
#define OVFMAX 8192

// ---------------------------------------------------------------------------
// Scratch — SLOT-MAJOR 32B records (one sector each):
//   uint4 #0 : v0v1, v2v3, v4v5, v6v7   (half2 bit patterns)
//   uint4 #1 : v8v9 (half2), rx (f32 bits), ry (f32 bits), pad
// ---------------------------------------------------------------------------
__device__ uint32_t g_cursor[TCELLS];
__device__ __align__(128) uint4 g_pay[(size_t)CAP * TCELLS * 2];   // 512 MB
__device__ uint32_t g_ovf_cnt;
__device__ float g_ovf[OVFMAX][16];   // cellg(bits), rx, ry, v0..v9

#define CUR4  (TCELLS / 4)
__global__ __launch_bounds__(256)
void zero_cursor_kernel() {
    const int i = blockIdx.x * blockDim.x + threadIdx.x;
    if (i < CUR4) ((uint4*)g_cursor)[i] = make_uint4(0u, 0u, 0u, 0u);
    if (i == 0) g_ovf_cnt = 0u;
}

// Zero only the tile frame: pixels with X%16==0 or Y%16==0 (atomic targets).
__global__ __launch_bounds__(256)
void zero_frame_kernel(float* __restrict__ out) {
    const int o = blockIdx.x * blockDim.x + threadIdx.x;
    if (o >= OUTN) return;
    const int idx = o & (CELLS - 1);
    const int X = idx & 255;
    const int Y = idx >> 8;
    if ((X & 15) == 0 || (Y & 15) == 0) out[o] = 0.f;
}

__device__ __forceinline__ uint32_t h2bits(float a, float b) {
    __half2 h = __floats2half2_rn(a, b);
    return *reinterpret_cast<uint32_t*>(&h);
}
__device__ __forceinline__ float2 bits2f2(uint32_t u) {
    __half2 h = *reinterpret_cast<__half2*>(&u);
    return __half22float2(h);
}

// ---------------------------------------------------------------------------
// Pass A: scatter into fixed-capacity slot-major buckets; overflow -> list
// ---------------------------------------------------------------------------
__global__ __launch_bounds__(256)
void scatter_kernel(const float* __restrict__ points,
                    const float* __restrict__ values) {
    const int gid = blockIdx.x * blockDim.x + threadIdx.x;
    const int b = gid >> 18;
    const int n = gid & (NPTS - 1);

    const float* pb = points + (size_t)b * 2 * NPTS;
    const float fx = (pb[n] + 0.5f) * (float)GS;
    const float fy = (pb[NPTS + n] + 0.5f) * (float)GS;
    const float xf = floorf(fx);
    const float yf = floorf(fy);
    const int x = (int)xf;
    const int y = (int)yf;
    const float rx = fx - xf;
    const float ry = fy - yf;
    if (((unsigned)x >= GS) || ((unsigned)y >= GS)) return;

    const float* vb = values + (size_t)b * NCLS * NPTS + n;
    float v[10];
#pragma unroll
    for (int c = 0; c < NCLS; c++) v[c] = vb[(size_t)c * NPTS];

    const int cellg = (b << 16) + (y << 8) + x;
    const uint32_t slot = atomicAdd(&g_cursor[cellg], 1u);

    if (slot < CAP) {
        uint4* dst = &g_pay[((size_t)slot * TCELLS + cellg) * 2];
        const uint4 q0 = make_uint4(h2bits(v[0], v[1]), h2bits(v[2], v[3]),
                                    h2bits(v[4], v[5]), h2bits(v[6], v[7]));
        const uint4 q1 = make_uint4(h2bits(v[8], v[9]),
                                    __float_as_uint(rx), __float_as_uint(ry), 0u);
        __stcs(dst + 0, q0);
        __stcs(dst + 1, q1);
    } else {
        const uint32_t oi = atomicAdd(&g_ovf_cnt, 1u);
        if (oi < OVFMAX) {
            float* r = g_ovf[oi];
            r[0] = __uint_as_float((uint32_t)cellg);
            r[1] = rx;  r[2] = ry;
#pragma unroll
            for (int c = 0; c < NCLS; c++) r[3 + c] = v[c];
        }
    }
}

// ---------------------------------------------------------------------------
// Pass B: fused reduce + corner-combine, one THREAD per CELL.
// Unroll-2 batched loads; pointer-increment addressing (no per-iter IMAD.wide);
// epilogue iterates positions (289) with a 10-class inner loop.
// ---------------------------------------------------------------------------
__global__ __launch_bounds__(256, 4)
void reduce_kernel(float* __restrict__ out) {
    const int t = threadIdx.x;
    const int ly = t >> 4;
    const int lx = t & 15;

    const int blk = blockIdx.x;        // 0..4095
    const int b  = blk >> 8;
    const int tt = blk & 255;
    const int ty = tt >> 4;
    const int tx = tt & 15;

    const int cellg = (b << 16) + ((ty * 16 + ly) << 8) + (tx * 16 + lx);
    const uint32_t raw = g_cursor[cellg];
    const uint32_t cnt = raw < CAP ? raw : CAP;
    const uint32_t wmax = __reduce_max_sync(0xFFFFFFFFu, cnt);

    float acc[4][NCLS];
#pragma unroll
    for (int k = 0; k < 4; k++)
#pragma unroll
        for (int c = 0; c < NCLS; c++) acc[k][c] = 0.f;

    // slot stride in uint4 units
    const size_t SSTR = (size_t)TCELLS * 2;
    const uint4* pa = &g_pay[(size_t)cellg * 2];          // slot 0
    const uint4* pb2p = pa + SSTR;                        // slot 1

    for (uint32_t i = 0; i < wmax; i += 2) {
        uint4 q0a, q1a, q0b, q1b;
        const bool pa_on = (i < cnt);
        const bool pb_on = (i + 1 < cnt);
        if (pa_on) {                    // batch both records' loads first (MLP)
            q0a = __ldcs(pa + 0);
            q1a = __ldcs(pa + 1);
        }
        if (pb_on) {
            q0b = __ldcs(pb2p + 0);
            q1b = __ldcs(pb2p + 1);
        }
        pa    += 2 * SSTR;
        pb2p  += 2 * SSTR;
        if (pa_on) {
            const float2 f01 = bits2f2(q0a.x), f23 = bits2f2(q0a.y);
            const float2 f45 = bits2f2(q0a.z), f67 = bits2f2(q0a.w);
            const float2 f89 = bits2f2(q1a.x);
            const float rx = __uint_as_float(q1a.y);
            const float ry = __uint_as_float(q1a.z);
            const float wx0 = 1.f - rx, wy0 = 1.f - ry;
            const float w00 = wx0 * wy0, w10 = rx * wy0, w01 = wx0 * ry, w11 = rx * ry;
            const float v[10] = {f01.x, f01.y, f23.x, f23.y, f45.x,
                                 f45.y, f67.x, f67.y, f89.x, f89.y};
#pragma unroll
            for (int c = 0; c < NCLS; c++) {
                acc[0][c] += w00 * v[c];
                acc[1][c] += w10 * v[c];
                acc[2][c] += w01 * v[c];
                acc[3][c] += w11 * v[c];
            }
        }
        if (pb_on) {
            const float2 f01 = bits2f2(q0b.x), f23 = bits2f2(q0b.y);
            const float2 f45 = bits2f2(q0b.z), f67 = bits2f2(q0b.w);
            const float2 f89 = bits2f2(q1b.x);
            const float rx = __uint_as_float(q1b.y);
            const float ry = __uint_as_float(q1b.z);
            const float wx0 = 1.f - rx, wy0 = 1.f - ry;
            const float w00 = wx0 * wy0, w10 = rx * wy0, w01 = wx0 * ry, w11 = rx * ry;
            const float v[10] = {f01.x, f01.y, f23.x, f23.y, f45.x,
                                 f45.y, f67.x, f67.y, f89.x, f89.y};
#pragma unroll
            for (int c = 0; c < NCLS; c++) {
                acc[0][c] += w00 * v[c];
                acc[1][c] += w10 * v[c];
                acc[2][c] += w01 * v[c];
                acc[3][c] += w11 * v[c];
            }
        }
    }

    // stage: st[corner][class][cell] (stride-1 in cell -> conflict-free)
    __shared__ float st[4][NCLS][256];
#pragma unroll
    for (int k = 0; k < 4; k++)
#pragma unroll
        for (int c = 0; c < NCLS; c++) st[k][c][t] = acc[k][c];
    __syncthreads();

    // assemble 17x17 patch: loop positions (289), inner loop classes (10).
    for (int pos = t; pos < 17 * 17; pos += 256) {
        const int oy = pos / 17;
        const int ox = pos - 17 * oy;

        const int Y = ty * 16 + oy;
        const int X = tx * 16 + ox;
        if (Y > 255 || X > 255) continue;

        const bool in00 = (oy < 16 && ox < 16);
        const bool in10 = (oy < 16 && ox >= 1);
        const bool in01 = (oy >= 1 && ox < 16);
        const bool in11 = (oy >= 1 && ox >= 1);
        const int i00 = oy * 16 + ox;
        const int i10 = i00 - 1;
        const int i01 = i00 - 16;
        const int i11 = i00 - 17;
        const bool excl = (oy != 16) && (ox != 16) &&
                          (oy != 0 || ty == 0) && (ox != 0 || tx == 0);

        float* dst = out + (((size_t)(b * NCLS)) << 16) + (Y << 8) + X;
#pragma unroll
        for (int c = 0; c < NCLS; c++) {
            float v = 0.f;
            if (in00) v += st[0][c][i00];
            if (in10) v += st[1][c][i10];
            if (in01) v += st[2][c][i01];
            if (in11) v += st[3][c][i11];
            if (excl) *dst = v;         // pure store (frame pre-zeroed)
            else      atomicAdd(dst, v);
            dst += CELLS;
        }
    }
}

// ---------------------------------------------------------------------------
// Pass C: apply rare overflow records with direct atomics (after reduce)
// ---------------------------------------------------------------------------
__global__ __launch_bounds__(256)
void ovf_kernel(float* __restrict__ out) {
    const uint32_t cnt = g_ovf_cnt < OVFMAX ? g_ovf_cnt : OVFMAX;
    for (uint32_t i = threadIdx.x; i < cnt; i += 256) {
        const float* r = g_ovf[i];
        const uint32_t cellg = __float_as_uint(r[0]);
        const int b = cellg >> 16;
        const int y = (cellg >> 8) & 255;
        const int x = cellg & 255;
        const float rx = r[1], ry = r[2];
        const bool vx1 = (x + 1) < GS;
        const bool vy1 = (y + 1) < GS;
        const float wx0 = 1.f - rx, wy0 = 1.f - ry;
        const float w00 = wx0 * wy0, w10 = rx * wy0, w01 = wx0 * ry, w11 = rx * ry;
        const int i00 = (y << 8) + x;
        float* ob = out + (size_t)b * NCLS * CELLS;
#pragma unroll
        for (int c = 0; c < NCLS; c++) {
            const float v = r[3 + c];
            float* o = ob + ((size_t)c << 16);
            atomicAdd(o + i00, w00 * v);
            if (vx1)        atomicAdd(o + i00 + 1,      w10 * v);
            if (vy1)        atomicAdd(o + i00 + GS,     w01 * v);
            if (vx1 && vy1) atomicAdd(o + i00 + GS + 1, w11 * v);
        }
    }
}

// ---------------------------------------------------------------------------
// Harness entry. Launch order puts reduce at idx 3 (ncu capture slot).
// ---------------------------------------------------------------------------
extern "C" void kernel_launch(void* const* d_in, const int* in_sizes, int n_in,
                              void* d_out, int out_size) {
    const float* points = (const float*)d_in[0];
    const float* values = (const float*)d_in[1];
    float* out = (float*)d_out;

    zero_frame_kernel<<<(OUTN + 255) / 256, 256>>>(out);                 // idx 0
    zero_cursor_kernel<<<(CUR4 + 255) / 256, 256>>>();                   // idx 1
    scatter_kernel<<<PTOT / 256, 256>>>(points, values);                 // idx 2
    reduce_kernel<<<TCELLS / 256, 256>>>(out);                           // idx 3 (profiled)
    ovf_kernel<<<1, 256>>>(out);                                         // idx 4
}